// round 16
// baseline (speedup 1.0000x reference)
#include <cuda_runtime.h>
#include <cuda_fp16.h>
#include <cstdint>

#define D_MODEL 1024
#define N_HEADS 16
#define DK      64
#define SEQ     2048
#define BATCH   2
#define ROWS    (BATCH * SEQ)          /* 4096 */
#define BH      (BATCH * N_HEADS)      /* 32 */
#define LN_EPS  1e-5f

#define SY ((long long)ROWS * D_MODEL)                         /* 4194304  */
#define SA ((long long)BH * SEQ * SEQ)                         /* 134217728 */

// ---------------- scratch (static device globals: no runtime alloc) --------
__device__ __half g_q  [ROWS * D_MODEL];              // fp16 Q
__device__ __half g_k  [ROWS * D_MODEL];              // fp16 K
__device__ __half g_v  [ROWS * D_MODEL];              // fp16 V
__device__ __half g_vt [ROWS * D_MODEL];              // fp16 V^T per head
__device__ __half g_xh [ROWS * D_MODEL];              // fp16 x
__device__ __half g_wh [4 * D_MODEL * D_MODEL];       // fp16 Wq,Wk,Wv,Wo
__device__ __half g_ch [ROWS * D_MODEL];              // fp16 ctx
__device__ __half g_sch[(size_t)BH * SEQ * SEQ];      // fp16 exp-scores 256MB
__device__ float  g_o  [ROWS * D_MODEL];
__device__ float  g_sc [(size_t)BH * SEQ * SEQ];      // f32 attn fallback
__device__ float  g_l  [BH * SEQ];                    // row sums of exp

// ---------------- helpers --------------------------------------------------
__device__ __forceinline__ void cp16(void* smem, const void* g) {
    uint32_t a = (uint32_t)__cvta_generic_to_shared(smem);
    asm volatile("cp.async.cg.shared.global [%0], [%1], 16;" :: "r"(a), "l"(g));
}
#define CP_COMMIT()  asm volatile("cp.async.commit_group;")
#define CP_WAIT(n)   asm volatile("cp.async.wait_group %0;" :: "n"(n))

// fp16 MMA, f32 accumulate, K=16
__device__ __forceinline__ void mma_f16(float c[4],
    uint32_t a0, uint32_t a1, uint32_t a2, uint32_t a3,
    uint32_t b0, uint32_t b1)
{
    asm volatile(
        "mma.sync.aligned.m16n8k16.row.col.f32.f16.f16.f32 "
        "{%0,%1,%2,%3}, {%4,%5,%6,%7}, {%8,%9}, {%0,%1,%2,%3};"
        : "+f"(c[0]), "+f"(c[1]), "+f"(c[2]), "+f"(c[3])
        : "r"(a0), "r"(a1), "r"(a2), "r"(a3), "r"(b0), "r"(b1));
}

__device__ __forceinline__ float warpReduceSum(float v) {
#pragma unroll
    for (int o = 16; o > 0; o >>= 1) v += __shfl_xor_sync(0xffffffffu, v, o);
    return v;
}
__device__ __forceinline__ float blockReduceSum(float v) {
    __shared__ float sh[8];
    __shared__ float res;
    int lane = threadIdx.x & 31, w = threadIdx.x >> 5;
    v = warpReduceSum(v);
    if (lane == 0) sh[w] = v;
    __syncthreads();
    if (w == 0) {
        float t = (lane < 8) ? sh[lane] : 0.0f;
        t = warpReduceSum(t);
        if (lane == 0) res = t;
    }
    __syncthreads();
    float r = res;
    __syncthreads();
    return r;
}

// ---------------- convert x + 4 weights to fp16 (one launch) ---------------
#define NX4 ((int)(SY / 4))
#define NW4 (D_MODEL * D_MODEL / 4)
__global__ void __launch_bounds__(256)
convert_h(const float4* __restrict__ x,
          const float4* __restrict__ Wq, const float4* __restrict__ Wk,
          const float4* __restrict__ Wv, const float4* __restrict__ Wo,
          __half2* __restrict__ xh, __half2* __restrict__ wh)
{
    int n4 = NX4 + 4 * NW4;
    for (int i = blockIdx.x * blockDim.x + threadIdx.x; i < n4;
         i += gridDim.x * blockDim.x) {
        const float4* src;
        __half2* dst;
        if (i < NX4) { src = x + i; dst = xh + 2 * (long long)i; }
        else {
            int j = i - NX4;
            int ws = j / NW4, off = j - ws * NW4;
            src = (ws == 0 ? Wq : ws == 1 ? Wk : ws == 2 ? Wv : Wo) + off;
            dst = wh + 2 * ((long long)ws * NW4 + off);
        }
        float4 v = *src;
        dst[0] = __floats2half2_rn(v.x, v.y);
        dst[1] = __floats2half2_rn(v.z, v.w);
    }
}

// ---------------- fp16 GEMM NT core (projections) --------------------------
#define PSTRH 40
template<bool OUTH>
__device__ __forceinline__ void gemm_nt_h(
    const __half* __restrict__ A, int lda,
    const __half* __restrict__ B, int ldb,
    void* __restrict__ Cv, int ldc, int K)
{
    __shared__ __half As[2][128 * PSTRH];
    __shared__ __half Bs[2][128 * PSTRH];

    int t    = threadIdx.x;
    int w    = t >> 5, lane = t & 31;
    int wm   = w >> 2, wn = w & 3;
    int g    = lane >> 2, tg = lane & 3;

    const __half* Ag = A + (long long)(blockIdx.y * 128) * lda;
    const __half* Bg = B + (long long)(blockIdx.x * 128) * ldb;

    int lr = t >> 1;
    int lc = (t & 1) * 16;

    float acc[4][4][4];
#pragma unroll
    for (int i = 0; i < 4; i++)
#pragma unroll
        for (int j = 0; j < 4; j++)
#pragma unroll
            for (int q = 0; q < 4; q++) acc[i][j][q] = 0.0f;

    auto load_tile = [&](int kt, int s) {
        long long ko = (long long)kt * 32;
        cp16(&As[s][lr * PSTRH + lc],     Ag + (long long)lr * lda + ko + lc);
        cp16(&As[s][lr * PSTRH + lc + 8], Ag + (long long)lr * lda + ko + lc + 8);
        cp16(&Bs[s][lr * PSTRH + lc],     Bg + (long long)lr * ldb + ko + lc);
        cp16(&Bs[s][lr * PSTRH + lc + 8], Bg + (long long)lr * ldb + ko + lc + 8);
    };

    int KT = K / 32;
    load_tile(0, 0);
    CP_COMMIT();

    for (int kt = 0; kt < KT; kt++) {
        if (kt + 1 < KT) load_tile(kt + 1, (kt + 1) & 1);
        CP_COMMIT();
        CP_WAIT(1);
        __syncthreads();

        const __half* as = As[kt & 1];
        const __half* bs = Bs[kt & 1];

#pragma unroll
        for (int kh = 0; kh < 2; kh++) {
            int kk = kh * 16;
            uint32_t af[4][4];
#pragma unroll
            for (int i = 0; i < 4; i++) {
                int r = wm * 64 + i * 16 + g;
                af[i][0] = *(const uint32_t*)&as[r * PSTRH + kk + 2 * tg];
                af[i][1] = *(const uint32_t*)&as[(r + 8) * PSTRH + kk + 2 * tg];
                af[i][2] = *(const uint32_t*)&as[r * PSTRH + kk + 8 + 2 * tg];
                af[i][3] = *(const uint32_t*)&as[(r + 8) * PSTRH + kk + 8 + 2 * tg];
            }
            uint32_t bf[4][2];
#pragma unroll
            for (int j = 0; j < 4; j++) {
                int n = wn * 32 + j * 8 + g;
                bf[j][0] = *(const uint32_t*)&bs[n * PSTRH + kk + 2 * tg];
                bf[j][1] = *(const uint32_t*)&bs[n * PSTRH + kk + 8 + 2 * tg];
            }
#pragma unroll
            for (int i = 0; i < 4; i++)
#pragma unroll
                for (int j = 0; j < 4; j++)
                    mma_f16(acc[i][j], af[i][0], af[i][1], af[i][2], af[i][3],
                            bf[j][0], bf[j][1]);
        }
        __syncthreads();
    }

#pragma unroll
    for (int i = 0; i < 4; i++) {
        long long r0 = blockIdx.y * 128 + wm * 64 + i * 16 + g;
#pragma unroll
        for (int j = 0; j < 4; j++) {
            int col = blockIdx.x * 128 + wn * 32 + j * 8 + tg * 2;
            if (OUTH) {
                __half* C = (__half*)Cv;
                *(__half2*)(C + r0 * ldc + col) =
                    __floats2half2_rn(acc[i][j][0], acc[i][j][1]);
                *(__half2*)(C + (r0 + 8) * ldc + col) =
                    __floats2half2_rn(acc[i][j][2], acc[i][j][3]);
            } else {
                float* C = (float*)Cv;
                *(float2*)(C + r0 * ldc + col) =
                    make_float2(acc[i][j][0], acc[i][j][1]);
                *(float2*)(C + (r0 + 8) * ldc + col) =
                    make_float2(acc[i][j][2], acc[i][j][3]);
            }
        }
    }
}

__global__ void __launch_bounds__(256)
qkv_proj_h(const __half* __restrict__ xh, const __half* __restrict__ wh,
           __half* __restrict__ q, __half* __restrict__ k, __half* __restrict__ v)
{
    const __half* B = wh + (long long)blockIdx.z * D_MODEL * D_MODEL;
    __half*       C = (blockIdx.z == 0) ? q : (blockIdx.z == 1) ? k : v;
    gemm_nt_h<true>(xh, D_MODEL, B, D_MODEL, C, D_MODEL, D_MODEL);
}

__global__ void __launch_bounds__(256)
out_proj_h(const __half* __restrict__ ch, const __half* __restrict__ wh,
           float* __restrict__ o)
{
    gemm_nt_h<false>(ch, D_MODEL, wh + 3LL * D_MODEL * D_MODEL,
                     D_MODEL, o, D_MODEL, D_MODEL);
}

// ---------------- fp16 scores: sc = half(exp(QK^T/8)), l += rowsum ---------
#define HS 72
#define SSTG 136
#define SC_SMEM (2 * 128 * HS * 2)
__global__ void __launch_bounds__(256)
scores_exp_h(const __half* __restrict__ q, const __half* __restrict__ k,
             __half* __restrict__ sc, float* __restrict__ l)
{
    extern __shared__ char sraw[];
    __half* Qs    = (__half*)sraw;          // 128 x HS
    __half* Ksm   = Qs + 128 * HS;          // 128 x HS
    __half* stage = (__half*)sraw;          // aliases Qs/Ksm after MMA

    int z = blockIdx.z, zb = z >> 4, zh = z & 15;
    const long long SBH = (long long)SEQ * D_MODEL;
    const __half* qb = q + (long long)zb * SBH + zh * DK
                         + (long long)(blockIdx.y * 128) * D_MODEL;
    const __half* kb = k + (long long)zb * SBH + zh * DK
                         + (long long)(blockIdx.x * 128) * D_MODEL;

    int t = threadIdx.x, w = t >> 5, lane = t & 31;
    int wm = w >> 2, wn = w & 3;
    int g = lane >> 2, tg = lane & 3;

#pragma unroll
    for (int i = t; i < 1024; i += 256) {
        int r = i >> 3, c8 = (i & 7) * 8;
        cp16(&Qs[r * HS + c8],  qb + (long long)r * D_MODEL + c8);
        cp16(&Ksm[r * HS + c8], kb + (long long)r * D_MODEL + c8);
    }
    CP_COMMIT();
    CP_WAIT(0);
    __syncthreads();

    float c[4][4][4];
#pragma unroll
    for (int i = 0; i < 4; i++)
#pragma unroll
        for (int j = 0; j < 4; j++)
#pragma unroll
            for (int qq = 0; qq < 4; qq++) c[i][j][qq] = 0.0f;

#pragma unroll
    for (int ks = 0; ks < 4; ks++) {
        int k0 = ks * 16;
        uint32_t af[4][4];
#pragma unroll
        for (int i = 0; i < 4; i++) {
            int r = wm * 64 + i * 16 + g;
            af[i][0] = *(const uint32_t*)&Qs[r * HS + k0 + 2 * tg];
            af[i][1] = *(const uint32_t*)&Qs[(r + 8) * HS + k0 + 2 * tg];
            af[i][2] = *(const uint32_t*)&Qs[r * HS + k0 + 8 + 2 * tg];
            af[i][3] = *(const uint32_t*)&Qs[(r + 8) * HS + k0 + 8 + 2 * tg];
        }
#pragma unroll
        for (int j = 0; j < 4; j++) {
            int n = wn * 32 + j * 8 + g;
            uint32_t b0 = *(const uint32_t*)&Ksm[n * HS + k0 + 2 * tg];
            uint32_t b1 = *(const uint32_t*)&Ksm[n * HS + k0 + 8 + 2 * tg];
#pragma unroll
            for (int i = 0; i < 4; i++)
                mma_f16(c[i][j], af[i][0], af[i][1], af[i][2], af[i][3], b0, b1);
        }
    }
    __syncthreads();   // Qs/Ksm dead -> stage may overwrite

    float* lb = l + (long long)z * SEQ + blockIdx.y * 128;
#pragma unroll
    for (int i = 0; i < 4; i++) {
        int rl = wm * 64 + i * 16 + g;
        float s0 = 0.0f, s1 = 0.0f;
#pragma unroll
        for (int j = 0; j < 4; j++) {
            float e0 = __expf(c[i][j][0] * 0.125f);
            float e1 = __expf(c[i][j][1] * 0.125f);
            float e2 = __expf(c[i][j][2] * 0.125f);
            float e3 = __expf(c[i][j][3] * 0.125f);
            int col = wn * 32 + j * 8 + 2 * tg;
            *(__half2*)&stage[rl * SSTG + col]       = __floats2half2_rn(e0, e1);
            *(__half2*)&stage[(rl + 8) * SSTG + col] = __floats2half2_rn(e2, e3);
            s0 += e0 + e1;
            s1 += e2 + e3;
        }
        s0 += __shfl_xor_sync(0xffffffffu, s0, 1);
        s0 += __shfl_xor_sync(0xffffffffu, s0, 2);
        s1 += __shfl_xor_sync(0xffffffffu, s1, 1);
        s1 += __shfl_xor_sync(0xffffffffu, s1, 2);
        if (tg == 0) {
            atomicAdd(&lb[rl],     s0);
            atomicAdd(&lb[rl + 8], s1);
        }
    }
    __syncthreads();

    __half* cb = sc + (long long)z * SEQ * SEQ
                    + (long long)(blockIdx.y * 128) * SEQ + blockIdx.x * 128;
#pragma unroll
    for (int i = t; i < 2048; i += 256) {
        int r = i >> 4, c8 = (i & 15) * 8;
        __stcs((float4*)&cb[(long long)r * SEQ + c8],
               *(const float4*)&stage[r * SSTG + c8]);
    }
}

// ---------------- per-head V transpose (fp16): Vt[bh][d][s] ----------------
__global__ void __launch_bounds__(256)
transpose_v_h(const __half* __restrict__ v, __half* __restrict__ vt)
{
    __shared__ __half tile[32][34];
    int bh = blockIdx.z;
    int b = bh >> 4, h = bh & 15;
    int s0 = blockIdx.x * 32, d0 = blockIdx.y * 32;
    int tx = threadIdx.x, ty = threadIdx.y;

    const __half* src = v + (long long)b * SEQ * D_MODEL + h * DK;
#pragma unroll
    for (int i = ty; i < 32; i += 8)
        tile[i][tx] = src[(long long)(s0 + i) * D_MODEL + d0 + tx];
    __syncthreads();
    __half* dst = vt + (long long)bh * DK * SEQ;
#pragma unroll
    for (int i = ty; i < 32; i += 8)
        dst[(long long)(d0 + i) * SEQ + s0 + tx] = tile[tx][i];
}

// ---------------- fused: attn emit + ctx = expP @ V (fp16, 3-stage) --------
#define FH 72
#define FC_SMEM (3 * (128 * FH + 64 * FH) * 2 + 128 * 4)   /* 83456 B */

__global__ void __launch_bounds__(256)
fused_ctx_h(const __half* __restrict__ expsc, const float* __restrict__ lsum,
            const __half* __restrict__ vt, float* __restrict__ attn,
            __half* __restrict__ ctx)
{
    extern __shared__ char smraw[];
    __half* Abuf[3];
    __half* Bbuf[3];
    {
        __half* p = (__half*)smraw;
        for (int s = 0; s < 3; s++) {
            Abuf[s] = p;            p += 128 * FH;
            Bbuf[s] = p;            p += 64 * FH;
        }
    }
    float* invl = (float*)((__half*)smraw + 3 * (128 * FH + 64 * FH));

    int bh = blockIdx.y, b = bh >> 4, h = bh & 15;
    int q0 = blockIdx.x * 128;

    const __half* sc_b = expsc + ((long long)bh * SEQ + q0) * SEQ;
    const __half* vt_b = vt + (long long)bh * DK * SEQ;
    float* at_b = attn + ((long long)bh * SEQ + q0) * SEQ;

    int t = threadIdx.x, w = t >> 5, lane = t & 31;
    int wm = w >> 2, wn = w & 3;               // 2x4 warps: m64 x n16 tiles
    int g = lane >> 2, tg = lane & 3;

    auto loadChunk = [&](int s, int k0) {
        __half* Ad = Abuf[s];
        __half* Bd = Bbuf[s];
#pragma unroll
        for (int i = t; i < 1024; i += 256) {          // A: 128x64 halves
            int r = i >> 3, c8 = (i & 7) * 8;
            cp16(&Ad[r * FH + c8], sc_b + (long long)r * SEQ + k0 + c8);
        }
#pragma unroll
        for (int i = t; i < 512; i += 256) {           // B: 64x64 halves
            int r = i >> 3, c8 = (i & 7) * 8;
            cp16(&Bd[r * FH + c8], vt_b + (long long)r * SEQ + k0 + c8);
        }
    };

    if (t < 128) invl[t] = 1.0f / lsum[(long long)bh * SEQ + q0 + t];

    float acc[4][2][4];
#pragma unroll
    for (int i = 0; i < 4; i++)
#pragma unroll
        for (int j = 0; j < 2; j++)
#pragma unroll
            for (int qq = 0; qq < 4; qq++) acc[i][j][qq] = 0.0f;

    loadChunk(0, 0);
    CP_COMMIT();
    loadChunk(1, 64);
    CP_COMMIT();
    __syncthreads();   // invl visible

    const int NT = SEQ / 64;   // 32
    for (int kt = 0; kt < NT; kt++) {
        int k0 = kt * 64;
        int buf = kt % 3;

        if (kt + 2 < NT) {
            loadChunk((kt + 2) % 3, k0 + 128);
            CP_COMMIT();
        }
        // wait until chunk kt's group has landed
        int rem = NT - 1 - kt;
        if (rem >= 2)      { CP_WAIT(2); }
        else if (rem == 1) { CP_WAIT(1); }
        else               { CP_WAIT(0); }
        __syncthreads();

        __half* as = Abuf[buf];
        __half* bs = Bbuf[buf];

        // attn emit first (stores in flight during MMA): p = expP * invl
#pragma unroll
        for (int i = t; i < 1024; i += 256) {
            int r = i >> 3, c8 = (i & 7) * 8;
            float iv = invl[r];
            const __half2* ph = (const __half2*)&as[r * FH + c8];
            float* po = at_b + (long long)r * SEQ + k0 + c8;
            float4 o0, o1;
            float2 x0 = __half22float2(ph[0]);
            float2 x1 = __half22float2(ph[1]);
            float2 x2 = __half22float2(ph[2]);
            float2 x3 = __half22float2(ph[3]);
            o0.x = x0.x * iv; o0.y = x0.y * iv; o0.z = x1.x * iv; o0.w = x1.y * iv;
            o1.x = x2.x * iv; o1.y = x2.y * iv; o1.z = x3.x * iv; o1.w = x3.y * iv;
            __stcs((float4*)po, o0);
            __stcs((float4*)(po + 4), o1);
        }

        // ctx += expP @ Vt^T  (fp16 MMA, K=16 per step)
#pragma unroll
        for (int ks = 0; ks < 4; ks++) {
            int kk = ks * 16;
            uint32_t af[4][4];
#pragma unroll
            for (int i = 0; i < 4; i++) {
                int r = wm * 64 + i * 16 + g;
                af[i][0] = *(const uint32_t*)&as[r * FH + kk + 2 * tg];
                af[i][1] = *(const uint32_t*)&as[(r + 8) * FH + kk + 2 * tg];
                af[i][2] = *(const uint32_t*)&as[r * FH + kk + 8 + 2 * tg];
                af[i][3] = *(const uint32_t*)&as[(r + 8) * FH + kk + 8 + 2 * tg];
            }
#pragma unroll
            for (int j = 0; j < 2; j++) {
                int n = wn * 16 + j * 8 + g;
                uint32_t b0 = *(const uint32_t*)&bs[n * FH + kk + 2 * tg];
                uint32_t b1 = *(const uint32_t*)&bs[n * FH + kk + 8 + 2 * tg];
#pragma unroll
                for (int i = 0; i < 4; i++)
                    mma_f16(acc[i][j], af[i][0], af[i][1], af[i][2], af[i][3],
                            b0, b1);
            }
        }
        __syncthreads();   // before a later iteration's cp.async reuses buf
    }

    // ctx epilogue: scale by invl, emit fp16 (out_proj consumes fp16)
    __half* cb = ctx + ((long long)b * SEQ + q0) * D_MODEL + h * DK;
#pragma unroll
    for (int i = 0; i < 4; i++) {
        int r = wm * 64 + i * 16 + g;
        float iv0 = invl[r], iv1 = invl[r + 8];
#pragma unroll
        for (int j = 0; j < 2; j++) {
            int col = wn * 16 + j * 8 + tg * 2;
            *(__half2*)(cb + (long long)r * D_MODEL + col) =
                __floats2half2_rn(acc[i][j][0] * iv0, acc[i][j][1] * iv0);
            *(__half2*)(cb + (long long)(r + 8) * D_MODEL + col) =
                __floats2half2_rn(acc[i][j][2] * iv1, acc[i][j][3] * iv1);
        }
    }
}

// ---------------- bias + residual + LayerNorm ------------------------------
__global__ void __launch_bounds__(256)
bias_res_ln(const float* __restrict__ o, const float* __restrict__ x,
            const float* __restrict__ bo, const float* __restrict__ gamma,
            const float* __restrict__ beta, float* __restrict__ y)
{
    long long row = blockIdx.x;
    int tid = threadIdx.x;
    const float4* o4 = (const float4*)(o + row * D_MODEL);
    const float4* x4 = (const float4*)(x + row * D_MODEL);
    const float4* b4 = (const float4*)bo;
    const float4* g4 = (const float4*)gamma;
    const float4* be4 = (const float4*)beta;

    float4 ov = o4[tid], xv = x4[tid], bv = b4[tid];
    float4 v;
    v.x = ov.x + xv.x + bv.x;
    v.y = ov.y + xv.y + bv.y;
    v.z = ov.z + xv.z + bv.z;
    v.w = ov.w + xv.w + bv.w;

    float s  = v.x + v.y + v.z + v.w;
    float sq = v.x * v.x + v.y * v.y + v.z * v.z + v.w * v.w;
    s  = blockReduceSum(s);
    sq = blockReduceSum(sq);

    float mean = s * (1.0f / D_MODEL);
    float var  = sq * (1.0f / D_MODEL) - mean * mean;
    float rstd = rsqrtf(var + LN_EPS);

    float4 gv = g4[tid], bev = be4[tid];
    float4 r;
    r.x = (v.x - mean) * rstd * gv.x + bev.x;
    r.y = (v.y - mean) * rstd * gv.y + bev.y;
    r.z = (v.z - mean) * rstd * gv.z + bev.z;
    r.w = (v.w - mean) * rstd * gv.w + bev.w;
    ((float4*)(y + row * D_MODEL))[tid] = r;
}

// ---------------- launch ---------------------------------------------------
extern "C" void kernel_launch(void* const* d_in, const int* in_sizes, int n_in,
                              void* d_out, int out_size)
{
    const float* x     = (const float*)d_in[0];
    const float* Wq    = (const float*)d_in[1];
    const float* Wk    = (const float*)d_in[2];
    const float* Wv    = (const float*)d_in[3];
    const float* Wo    = (const float*)d_in[4];
    const float* bo    = (const float*)d_in[5];
    const float* gamma = (const float*)d_in[6];
    const float* beta  = (const float*)d_in[7];

    float* y_out    = (float*)d_out;
    float* attn_out = nullptr;
    if ((long long)out_size >= SY + SA) {
        attn_out = y_out + SY;                 // outputs concatenated: y, attn
    } else if ((long long)out_size == SA) {
        attn_out = y_out;                      // attn-only output
        y_out = nullptr;
    }

    __half *q, *k, *v, *vt, *xh, *wh, *ch, *sch;
    float *ob, *scf, *lptr;
    cudaGetSymbolAddress((void**)&q,    g_q);
    cudaGetSymbolAddress((void**)&k,    g_k);
    cudaGetSymbolAddress((void**)&v,    g_v);
    cudaGetSymbolAddress((void**)&vt,   g_vt);
    cudaGetSymbolAddress((void**)&xh,   g_xh);
    cudaGetSymbolAddress((void**)&wh,   g_wh);
    cudaGetSymbolAddress((void**)&ch,   g_ch);
    cudaGetSymbolAddress((void**)&sch,  g_sch);
    cudaGetSymbolAddress((void**)&ob,   g_o);
    cudaGetSymbolAddress((void**)&scf,  g_sc);
    cudaGetSymbolAddress((void**)&lptr, g_l);

    float* attn = attn_out ? attn_out : scf;

    static int init_done = 0;
    static cudaStream_t s2;
    static cudaEvent_t evA, evB;
    if (!init_done) {
        cudaFuncSetAttribute(fused_ctx_h,
            cudaFuncAttributeMaxDynamicSharedMemorySize, FC_SMEM);
        cudaFuncSetAttribute(scores_exp_h,
            cudaFuncAttributeMaxDynamicSharedMemorySize, SC_SMEM);
        cudaStreamCreateWithFlags(&s2, cudaStreamNonBlocking);
        cudaEventCreateWithFlags(&evA, cudaEventDisableTiming);
        cudaEventCreateWithFlags(&evB, cudaEventDisableTiming);
        init_done = 1;
    }

    cudaMemsetAsync(lptr, 0, (size_t)BH * SEQ * sizeof(float));

    // convert x + weights to fp16 (single launch)
    convert_h<<<2048, 256>>>((const float4*)x, (const float4*)Wq,
                             (const float4*)Wk, (const float4*)Wv,
                             (const float4*)Wo, (__half2*)xh, (__half2*)wh);

    // projections (fp16 MMA) -> fp16 q,k,v
    qkv_proj_h<<<dim3(8, 32, 3), 256>>>(xh, wh, q, k, v);

    // fork: transpose V on side stream, scores on main stream (independent)
    cudaEventRecord(evA, 0);
    cudaStreamWaitEvent(s2, evA, 0);
    transpose_v_h<<<dim3(SEQ / 32, DK / 32, BH), dim3(32, 8), 0, s2>>>(v, vt);
    cudaEventRecord(evB, s2);

    // fp16 exp-scores (staged coalesced stores) + f32 row sums
    scores_exp_h<<<dim3(16, 16, BH), 256, SC_SMEM>>>(q, k, sch, lptr);

    // join before fused consumer
    cudaStreamWaitEvent(0, evB, 0);

    // attn emit + ctx GEMM (fp16 MMA, 3-stage pipeline) -> fp16 ctx
    fused_ctx_h<<<dim3(16, BH), 256, FC_SMEM>>>(sch, lptr, vt, attn, ch);

    if (y_out) {
        out_proj_h<<<dim3(8, 32), 256>>>(ch, wh, ob);
        bias_res_ln<<<ROWS, 256>>>(ob, x, bo, gamma, beta, y_out);
    }
}

// round 17
// speedup vs baseline: 1.0719x; 1.0719x over previous
#include <cuda_runtime.h>
#include <cuda_fp16.h>
#include <cstdint>

#define D_MODEL 1024
#define N_HEADS 16
#define DK      64
#define SEQ     2048
#define BATCH   2
#define ROWS    (BATCH * SEQ)          /* 4096 */
#define BH      (BATCH * N_HEADS)      /* 32 */
#define LN_EPS  1e-5f

#define SY ((long long)ROWS * D_MODEL)                         /* 4194304  */
#define SA ((long long)BH * SEQ * SEQ)                         /* 134217728 */

// ---------------- scratch (static device globals: no runtime alloc) --------
__device__ __half g_q  [ROWS * D_MODEL];              // fp16 Q
__device__ __half g_k  [ROWS * D_MODEL];              // fp16 K
__device__ __half g_v  [ROWS * D_MODEL];              // fp16 V
__device__ __half g_vt [ROWS * D_MODEL];              // fp16 V^T per head
__device__ __half g_xh [ROWS * D_MODEL];              // fp16 x
__device__ __half g_wh [4 * D_MODEL * D_MODEL];       // fp16 Wq,Wk,Wv,Wo
__device__ __half g_ch [ROWS * D_MODEL];              // fp16 ctx
__device__ __half g_sch[(size_t)BH * SEQ * SEQ];      // fp16 exp-scores 256MB
__device__ float  g_o  [ROWS * D_MODEL];
__device__ float  g_sc [(size_t)BH * SEQ * SEQ];      // f32 attn fallback
__device__ float  g_l  [BH * SEQ];                    // row sums of exp

// ---------------- helpers --------------------------------------------------
__device__ __forceinline__ void cp16(void* smem, const void* g) {
    uint32_t a = (uint32_t)__cvta_generic_to_shared(smem);
    asm volatile("cp.async.cg.shared.global [%0], [%1], 16;" :: "r"(a), "l"(g));
}
#define CP_COMMIT()  asm volatile("cp.async.commit_group;")
#define CP_WAIT(n)   asm volatile("cp.async.wait_group %0;" :: "n"(n))

// fp16 MMA, f32 accumulate, K=16
__device__ __forceinline__ void mma_f16(float c[4],
    uint32_t a0, uint32_t a1, uint32_t a2, uint32_t a3,
    uint32_t b0, uint32_t b1)
{
    asm volatile(
        "mma.sync.aligned.m16n8k16.row.col.f32.f16.f16.f32 "
        "{%0,%1,%2,%3}, {%4,%5,%6,%7}, {%8,%9}, {%0,%1,%2,%3};"
        : "+f"(c[0]), "+f"(c[1]), "+f"(c[2]), "+f"(c[3])
        : "r"(a0), "r"(a1), "r"(a2), "r"(a3), "r"(b0), "r"(b1));
}

__device__ __forceinline__ float warpReduceSum(float v) {
#pragma unroll
    for (int o = 16; o > 0; o >>= 1) v += __shfl_xor_sync(0xffffffffu, v, o);
    return v;
}
__device__ __forceinline__ float blockReduceSum(float v) {
    __shared__ float sh[8];
    __shared__ float res;
    int lane = threadIdx.x & 31, w = threadIdx.x >> 5;
    v = warpReduceSum(v);
    if (lane == 0) sh[w] = v;
    __syncthreads();
    if (w == 0) {
        float t = (lane < 8) ? sh[lane] : 0.0f;
        t = warpReduceSum(t);
        if (lane == 0) res = t;
    }
    __syncthreads();
    float r = res;
    __syncthreads();
    return r;
}

// ---------------- convert x + 4 weights to fp16 (one launch) ---------------
#define NX4 ((int)(SY / 4))
#define NW4 (D_MODEL * D_MODEL / 4)
__global__ void __launch_bounds__(256)
convert_h(const float4* __restrict__ x,
          const float4* __restrict__ Wq, const float4* __restrict__ Wk,
          const float4* __restrict__ Wv, const float4* __restrict__ Wo,
          __half2* __restrict__ xh, __half2* __restrict__ wh)
{
    int n4 = NX4 + 4 * NW4;
    for (int i = blockIdx.x * blockDim.x + threadIdx.x; i < n4;
         i += gridDim.x * blockDim.x) {
        const float4* src;
        __half2* dst;
        if (i < NX4) { src = x + i; dst = xh + 2 * (long long)i; }
        else {
            int j = i - NX4;
            int ws = j / NW4, off = j - ws * NW4;
            src = (ws == 0 ? Wq : ws == 1 ? Wk : ws == 2 ? Wv : Wo) + off;
            dst = wh + 2 * ((long long)ws * NW4 + off);
        }
        float4 v = *src;
        dst[0] = __floats2half2_rn(v.x, v.y);
        dst[1] = __floats2half2_rn(v.z, v.w);
    }
}

// ---------------- fp16 GEMM NT core (projections) --------------------------
#define PSTRH 40
template<bool OUTH>
__device__ __forceinline__ void gemm_nt_h(
    const __half* __restrict__ A, int lda,
    const __half* __restrict__ B, int ldb,
    void* __restrict__ Cv, int ldc, int K)
{
    __shared__ __half As[2][128 * PSTRH];
    __shared__ __half Bs[2][128 * PSTRH];

    int t    = threadIdx.x;
    int w    = t >> 5, lane = t & 31;
    int wm   = w >> 2, wn = w & 3;
    int g    = lane >> 2, tg = lane & 3;

    const __half* Ag = A + (long long)(blockIdx.y * 128) * lda;
    const __half* Bg = B + (long long)(blockIdx.x * 128) * ldb;

    int lr = t >> 1;
    int lc = (t & 1) * 16;

    float acc[4][4][4];
#pragma unroll
    for (int i = 0; i < 4; i++)
#pragma unroll
        for (int j = 0; j < 4; j++)
#pragma unroll
            for (int q = 0; q < 4; q++) acc[i][j][q] = 0.0f;

    auto load_tile = [&](int kt, int s) {
        long long ko = (long long)kt * 32;
        cp16(&As[s][lr * PSTRH + lc],     Ag + (long long)lr * lda + ko + lc);
        cp16(&As[s][lr * PSTRH + lc + 8], Ag + (long long)lr * lda + ko + lc + 8);
        cp16(&Bs[s][lr * PSTRH + lc],     Bg + (long long)lr * ldb + ko + lc);
        cp16(&Bs[s][lr * PSTRH + lc + 8], Bg + (long long)lr * ldb + ko + lc + 8);
    };

    int KT = K / 32;
    load_tile(0, 0);
    CP_COMMIT();

    for (int kt = 0; kt < KT; kt++) {
        if (kt + 1 < KT) load_tile(kt + 1, (kt + 1) & 1);
        CP_COMMIT();
        CP_WAIT(1);
        __syncthreads();

        const __half* as = As[kt & 1];
        const __half* bs = Bs[kt & 1];

#pragma unroll
        for (int kh = 0; kh < 2; kh++) {
            int kk = kh * 16;
            uint32_t af[4][4];
#pragma unroll
            for (int i = 0; i < 4; i++) {
                int r = wm * 64 + i * 16 + g;
                af[i][0] = *(const uint32_t*)&as[r * PSTRH + kk + 2 * tg];
                af[i][1] = *(const uint32_t*)&as[(r + 8) * PSTRH + kk + 2 * tg];
                af[i][2] = *(const uint32_t*)&as[r * PSTRH + kk + 8 + 2 * tg];
                af[i][3] = *(const uint32_t*)&as[(r + 8) * PSTRH + kk + 8 + 2 * tg];
            }
            uint32_t bf[4][2];
#pragma unroll
            for (int j = 0; j < 4; j++) {
                int n = wn * 32 + j * 8 + g;
                bf[j][0] = *(const uint32_t*)&bs[n * PSTRH + kk + 2 * tg];
                bf[j][1] = *(const uint32_t*)&bs[n * PSTRH + kk + 8 + 2 * tg];
            }
#pragma unroll
            for (int i = 0; i < 4; i++)
#pragma unroll
                for (int j = 0; j < 4; j++)
                    mma_f16(acc[i][j], af[i][0], af[i][1], af[i][2], af[i][3],
                            bf[j][0], bf[j][1]);
        }
        __syncthreads();
    }

#pragma unroll
    for (int i = 0; i < 4; i++) {
        long long r0 = blockIdx.y * 128 + wm * 64 + i * 16 + g;
#pragma unroll
        for (int j = 0; j < 4; j++) {
            int col = blockIdx.x * 128 + wn * 32 + j * 8 + tg * 2;
            if (OUTH) {
                __half* C = (__half*)Cv;
                *(__half2*)(C + r0 * ldc + col) =
                    __floats2half2_rn(acc[i][j][0], acc[i][j][1]);
                *(__half2*)(C + (r0 + 8) * ldc + col) =
                    __floats2half2_rn(acc[i][j][2], acc[i][j][3]);
            } else {
                float* C = (float*)Cv;
                *(float2*)(C + r0 * ldc + col) =
                    make_float2(acc[i][j][0], acc[i][j][1]);
                *(float2*)(C + (r0 + 8) * ldc + col) =
                    make_float2(acc[i][j][2], acc[i][j][3]);
            }
        }
    }
}

__global__ void __launch_bounds__(256)
qkv_proj_h(const __half* __restrict__ xh, const __half* __restrict__ wh,
           __half* __restrict__ q, __half* __restrict__ k, __half* __restrict__ v)
{
    const __half* B = wh + (long long)blockIdx.z * D_MODEL * D_MODEL;
    __half*       C = (blockIdx.z == 0) ? q : (blockIdx.z == 1) ? k : v;
    gemm_nt_h<true>(xh, D_MODEL, B, D_MODEL, C, D_MODEL, D_MODEL);
}

__global__ void __launch_bounds__(256)
out_proj_h(const __half* __restrict__ ch, const __half* __restrict__ wh,
           float* __restrict__ o)
{
    gemm_nt_h<false>(ch, D_MODEL, wh + 3LL * D_MODEL * D_MODEL,
                     D_MODEL, o, D_MODEL, D_MODEL);
}

// ---------------- fp16 scores: sc = half(exp(QK^T/8)), l += rowsum ---------
// n-dimension split into two sequential halves: only c[4][2][4] accumulators
// live at a time -> lower register pressure -> 3 CTAs/SM. Stage buffer is
// separate from Q/K (both halves still need Q/K).
#define HS 72
#define SSTG 136
#define SC_SMEM ((2 * 128 * HS + 128 * SSTG) * 2)   /* 71680 B */
__global__ void __launch_bounds__(256, 3)
scores_exp_h(const __half* __restrict__ q, const __half* __restrict__ k,
             __half* __restrict__ sc, float* __restrict__ l)
{
    extern __shared__ char sraw[];
    __half* Qs    = (__half*)sraw;          // 128 x HS
    __half* Ksm   = Qs + 128 * HS;          // 128 x HS
    __half* stage = Ksm + 128 * HS;         // 128 x SSTG

    int z = blockIdx.z, zb = z >> 4, zh = z & 15;
    const long long SBH = (long long)SEQ * D_MODEL;
    const __half* qb = q + (long long)zb * SBH + zh * DK
                         + (long long)(blockIdx.y * 128) * D_MODEL;
    const __half* kb = k + (long long)zb * SBH + zh * DK
                         + (long long)(blockIdx.x * 128) * D_MODEL;

    int t = threadIdx.x, w = t >> 5, lane = t & 31;
    int wm = w >> 2, wn = w & 3;
    int g = lane >> 2, tg = lane & 3;

#pragma unroll
    for (int i = t; i < 1024; i += 256) {
        int r = i >> 3, c8 = (i & 7) * 8;
        cp16(&Qs[r * HS + c8],  qb + (long long)r * D_MODEL + c8);
        cp16(&Ksm[r * HS + c8], kb + (long long)r * D_MODEL + c8);
    }
    CP_COMMIT();
    CP_WAIT(0);
    __syncthreads();

    float rs0[4], rs1[4];
#pragma unroll
    for (int i = 0; i < 4; i++) { rs0[i] = 0.0f; rs1[i] = 0.0f; }

#pragma unroll
    for (int nh = 0; nh < 2; nh++) {
        float c[4][2][4];
#pragma unroll
        for (int i = 0; i < 4; i++)
#pragma unroll
            for (int j = 0; j < 2; j++)
#pragma unroll
                for (int qq = 0; qq < 4; qq++) c[i][j][qq] = 0.0f;

#pragma unroll
        for (int ks = 0; ks < 4; ks++) {
            int k0 = ks * 16;
            uint32_t af[4][4];
#pragma unroll
            for (int i = 0; i < 4; i++) {
                int r = wm * 64 + i * 16 + g;
                af[i][0] = *(const uint32_t*)&Qs[r * HS + k0 + 2 * tg];
                af[i][1] = *(const uint32_t*)&Qs[(r + 8) * HS + k0 + 2 * tg];
                af[i][2] = *(const uint32_t*)&Qs[r * HS + k0 + 8 + 2 * tg];
                af[i][3] = *(const uint32_t*)&Qs[(r + 8) * HS + k0 + 8 + 2 * tg];
            }
#pragma unroll
            for (int j2 = 0; j2 < 2; j2++) {
                int j = nh * 2 + j2;
                int n = wn * 32 + j * 8 + g;
                uint32_t b0 = *(const uint32_t*)&Ksm[n * HS + k0 + 2 * tg];
                uint32_t b1 = *(const uint32_t*)&Ksm[n * HS + k0 + 8 + 2 * tg];
#pragma unroll
                for (int i = 0; i < 4; i++)
                    mma_f16(c[i][j2], af[i][0], af[i][1], af[i][2], af[i][3],
                            b0, b1);
            }
        }

        // exp -> stage (smem), accumulate row sums
#pragma unroll
        for (int i = 0; i < 4; i++) {
            int rl = wm * 64 + i * 16 + g;
#pragma unroll
            for (int j2 = 0; j2 < 2; j2++) {
                int j = nh * 2 + j2;
                float e0 = __expf(c[i][j2][0] * 0.125f);
                float e1 = __expf(c[i][j2][1] * 0.125f);
                float e2 = __expf(c[i][j2][2] * 0.125f);
                float e3 = __expf(c[i][j2][3] * 0.125f);
                int col = wn * 32 + j * 8 + 2 * tg;
                *(__half2*)&stage[rl * SSTG + col]       = __floats2half2_rn(e0, e1);
                *(__half2*)&stage[(rl + 8) * SSTG + col] = __floats2half2_rn(e2, e3);
                rs0[i] += e0 + e1;
                rs1[i] += e2 + e3;
            }
        }
    }

    // row-sum atomics (order matches old kernel: j=0..3 accumulated per row)
    float* lb = l + (long long)z * SEQ + blockIdx.y * 128;
#pragma unroll
    for (int i = 0; i < 4; i++) {
        int rl = wm * 64 + i * 16 + g;
        float s0 = rs0[i], s1 = rs1[i];
        s0 += __shfl_xor_sync(0xffffffffu, s0, 1);
        s0 += __shfl_xor_sync(0xffffffffu, s0, 2);
        s1 += __shfl_xor_sync(0xffffffffu, s1, 1);
        s1 += __shfl_xor_sync(0xffffffffu, s1, 2);
        if (tg == 0) {
            atomicAdd(&lb[rl],     s0);
            atomicAdd(&lb[rl + 8], s1);
        }
    }
    __syncthreads();

    // coalesced 16B streaming stores: 128 rows x 128 halves
    __half* cb = sc + (long long)z * SEQ * SEQ
                    + (long long)(blockIdx.y * 128) * SEQ + blockIdx.x * 128;
#pragma unroll
    for (int i = t; i < 2048; i += 256) {
        int r = i >> 4, c8 = (i & 15) * 8;
        __stcs((float4*)&cb[(long long)r * SEQ + c8],
               *(const float4*)&stage[r * SSTG + c8]);
    }
}

// ---------------- per-head V transpose (fp16): Vt[bh][d][s] ----------------
__global__ void __launch_bounds__(256)
transpose_v_h(const __half* __restrict__ v, __half* __restrict__ vt)
{
    __shared__ __half tile[32][34];
    int bh = blockIdx.z;
    int b = bh >> 4, h = bh & 15;
    int s0 = blockIdx.x * 32, d0 = blockIdx.y * 32;
    int tx = threadIdx.x, ty = threadIdx.y;

    const __half* src = v + (long long)b * SEQ * D_MODEL + h * DK;
#pragma unroll
    for (int i = ty; i < 32; i += 8)
        tile[i][tx] = src[(long long)(s0 + i) * D_MODEL + d0 + tx];
    __syncthreads();
    __half* dst = vt + (long long)bh * DK * SEQ;
#pragma unroll
    for (int i = ty; i < 32; i += 8)
        dst[(long long)(d0 + i) * SEQ + s0 + tx] = tile[tx][i];
}

// ---------------- fused: attn emit + ctx = expP @ V (fp16 MMA) -------------
#define FH 72
#define FC_SMEM ((2 * 128 * FH + 2 * 64 * FH) * 2 + 128 * 4)

__global__ void __launch_bounds__(256)
fused_ctx_h(const __half* __restrict__ expsc, const float* __restrict__ lsum,
            const __half* __restrict__ vt, float* __restrict__ attn,
            __half* __restrict__ ctx)
{
    extern __shared__ char smraw[];
    __half* As0 = (__half*)smraw;               // 128 x 72
    __half* As1 = As0 + 128 * FH;
    __half* Bs0 = As1 + 128 * FH;               // 64 x 72
    __half* Bs1 = Bs0 + 64 * FH;
    float* invl = (float*)(Bs1 + 64 * FH);      // 128

    int bh = blockIdx.y, b = bh >> 4, h = bh & 15;
    int q0 = blockIdx.x * 128;

    const __half* sc_b = expsc + ((long long)bh * SEQ + q0) * SEQ;
    const __half* vt_b = vt + (long long)bh * DK * SEQ;
    float* at_b = attn + ((long long)bh * SEQ + q0) * SEQ;

    int t = threadIdx.x, w = t >> 5, lane = t & 31;
    int wm = w >> 2, wn = w & 3;               // 2x4 warps: m64 x n16 tiles
    int g = lane >> 2, tg = lane & 3;

    auto loadChunk = [&](__half* Ad, __half* Bd, int k0) {
#pragma unroll
        for (int i = t; i < 1024; i += 256) {          // A: 128x64 halves
            int r = i >> 3, c8 = (i & 7) * 8;
            cp16(&Ad[r * FH + c8], sc_b + (long long)r * SEQ + k0 + c8);
        }
#pragma unroll
        for (int i = t; i < 512; i += 256) {           // B: 64x64 halves
            int r = i >> 3, c8 = (i & 7) * 8;
            cp16(&Bd[r * FH + c8], vt_b + (long long)r * SEQ + k0 + c8);
        }
    };

    if (t < 128) invl[t] = 1.0f / lsum[(long long)bh * SEQ + q0 + t];

    float acc[4][2][4];
#pragma unroll
    for (int i = 0; i < 4; i++)
#pragma unroll
        for (int j = 0; j < 2; j++)
#pragma unroll
            for (int qq = 0; qq < 4; qq++) acc[i][j][qq] = 0.0f;

    loadChunk(As0, Bs0, 0);
    CP_COMMIT();
    __syncthreads();   // invl visible

    for (int kt = 0; kt < SEQ / 64; kt++) {
        int k0 = kt * 64;
        __half* as = (kt & 1) ? As1 : As0;
        __half* bs = (kt & 1) ? Bs1 : Bs0;

        if (kt < SEQ / 64 - 1) {
            loadChunk((kt & 1) ? As0 : As1, (kt & 1) ? Bs0 : Bs1, k0 + 64);
            CP_COMMIT();
            CP_WAIT(1);
        } else {
            CP_WAIT(0);
        }
        __syncthreads();

        // attn emit first (stores in flight during MMA): p = expP * invl
#pragma unroll
        for (int i = t; i < 1024; i += 256) {
            int r = i >> 3, c8 = (i & 7) * 8;
            float iv = invl[r];
            const __half2* ph = (const __half2*)&as[r * FH + c8];
            float* po = at_b + (long long)r * SEQ + k0 + c8;
            float4 o0, o1;
            float2 x0 = __half22float2(ph[0]);
            float2 x1 = __half22float2(ph[1]);
            float2 x2 = __half22float2(ph[2]);
            float2 x3 = __half22float2(ph[3]);
            o0.x = x0.x * iv; o0.y = x0.y * iv; o0.z = x1.x * iv; o0.w = x1.y * iv;
            o1.x = x2.x * iv; o1.y = x2.y * iv; o1.z = x3.x * iv; o1.w = x3.y * iv;
            __stcs((float4*)po, o0);
            __stcs((float4*)(po + 4), o1);
        }

        // ctx += expP @ Vt^T  (fp16 MMA, K=16 per step)
#pragma unroll
        for (int ks = 0; ks < 4; ks++) {
            int kk = ks * 16;
            uint32_t af[4][4];
#pragma unroll
            for (int i = 0; i < 4; i++) {
                int r = wm * 64 + i * 16 + g;
                af[i][0] = *(const uint32_t*)&as[r * FH + kk + 2 * tg];
                af[i][1] = *(const uint32_t*)&as[(r + 8) * FH + kk + 2 * tg];
                af[i][2] = *(const uint32_t*)&as[r * FH + kk + 8 + 2 * tg];
                af[i][3] = *(const uint32_t*)&as[(r + 8) * FH + kk + 8 + 2 * tg];
            }
#pragma unroll
            for (int j = 0; j < 2; j++) {
                int n = wn * 16 + j * 8 + g;
                uint32_t b0 = *(const uint32_t*)&bs[n * FH + kk + 2 * tg];
                uint32_t b1 = *(const uint32_t*)&bs[n * FH + kk + 8 + 2 * tg];
#pragma unroll
                for (int i = 0; i < 4; i++)
                    mma_f16(acc[i][j], af[i][0], af[i][1], af[i][2], af[i][3],
                            b0, b1);
            }
        }
        __syncthreads();   // before next iteration reuses buffers
    }

    // ctx epilogue: scale by invl, emit fp16 (out_proj consumes fp16)
    __half* cb = ctx + ((long long)b * SEQ + q0) * D_MODEL + h * DK;
#pragma unroll
    for (int i = 0; i < 4; i++) {
        int r = wm * 64 + i * 16 + g;
        float iv0 = invl[r], iv1 = invl[r + 8];
#pragma unroll
        for (int j = 0; j < 2; j++) {
            int col = wn * 16 + j * 8 + tg * 2;
            *(__half2*)(cb + (long long)r * D_MODEL + col) =
                __floats2half2_rn(acc[i][j][0] * iv0, acc[i][j][1] * iv0);
            *(__half2*)(cb + (long long)(r + 8) * D_MODEL + col) =
                __floats2half2_rn(acc[i][j][2] * iv1, acc[i][j][3] * iv1);
        }
    }
}

// ---------------- bias + residual + LayerNorm ------------------------------
__global__ void __launch_bounds__(256)
bias_res_ln(const float* __restrict__ o, const float* __restrict__ x,
            const float* __restrict__ bo, const float* __restrict__ gamma,
            const float* __restrict__ beta, float* __restrict__ y)
{
    long long row = blockIdx.x;
    int tid = threadIdx.x;
    const float4* o4 = (const float4*)(o + row * D_MODEL);
    const float4* x4 = (const float4*)(x + row * D_MODEL);
    const float4* b4 = (const float4*)bo;
    const float4* g4 = (const float4*)gamma;
    const float4* be4 = (const float4*)beta;

    float4 ov = o4[tid], xv = x4[tid], bv = b4[tid];
    float4 v;
    v.x = ov.x + xv.x + bv.x;
    v.y = ov.y + xv.y + bv.y;
    v.z = ov.z + xv.z + bv.z;
    v.w = ov.w + xv.w + bv.w;

    float s  = v.x + v.y + v.z + v.w;
    float sq = v.x * v.x + v.y * v.y + v.z * v.z + v.w * v.w;
    s  = blockReduceSum(s);
    sq = blockReduceSum(sq);

    float mean = s * (1.0f / D_MODEL);
    float var  = sq * (1.0f / D_MODEL) - mean * mean;
    float rstd = rsqrtf(var + LN_EPS);

    float4 gv = g4[tid], bev = be4[tid];
    float4 r;
    r.x = (v.x - mean) * rstd * gv.x + bev.x;
    r.y = (v.y - mean) * rstd * gv.y + bev.y;
    r.z = (v.z - mean) * rstd * gv.z + bev.z;
    r.w = (v.w - mean) * rstd * gv.w + bev.w;
    ((float4*)(y + row * D_MODEL))[tid] = r;
}

// ---------------- launch ---------------------------------------------------
extern "C" void kernel_launch(void* const* d_in, const int* in_sizes, int n_in,
                              void* d_out, int out_size)
{
    const float* x     = (const float*)d_in[0];
    const float* Wq    = (const float*)d_in[1];
    const float* Wk    = (const float*)d_in[2];
    const float* Wv    = (const float*)d_in[3];
    const float* Wo    = (const float*)d_in[4];
    const float* bo    = (const float*)d_in[5];
    const float* gamma = (const float*)d_in[6];
    const float* beta  = (const float*)d_in[7];

    float* y_out    = (float*)d_out;
    float* attn_out = nullptr;
    if ((long long)out_size >= SY + SA) {
        attn_out = y_out + SY;                 // outputs concatenated: y, attn
    } else if ((long long)out_size == SA) {
        attn_out = y_out;                      // attn-only output
        y_out = nullptr;
    }

    __half *q, *k, *v, *vt, *xh, *wh, *ch, *sch;
    float *ob, *scf, *lptr;
    cudaGetSymbolAddress((void**)&q,    g_q);
    cudaGetSymbolAddress((void**)&k,    g_k);
    cudaGetSymbolAddress((void**)&v,    g_v);
    cudaGetSymbolAddress((void**)&vt,   g_vt);
    cudaGetSymbolAddress((void**)&xh,   g_xh);
    cudaGetSymbolAddress((void**)&wh,   g_wh);
    cudaGetSymbolAddress((void**)&ch,   g_ch);
    cudaGetSymbolAddress((void**)&sch,  g_sch);
    cudaGetSymbolAddress((void**)&ob,   g_o);
    cudaGetSymbolAddress((void**)&scf,  g_sc);
    cudaGetSymbolAddress((void**)&lptr, g_l);

    float* attn = attn_out ? attn_out : scf;

    static int smem_set = 0;
    if (!smem_set) {
        cudaFuncSetAttribute(fused_ctx_h,
            cudaFuncAttributeMaxDynamicSharedMemorySize, FC_SMEM);
        cudaFuncSetAttribute(scores_exp_h,
            cudaFuncAttributeMaxDynamicSharedMemorySize, SC_SMEM);
        smem_set = 1;
    }

    cudaMemsetAsync(lptr, 0, (size_t)BH * SEQ * sizeof(float));

    // convert x + weights to fp16 (single launch)
    convert_h<<<2048, 256>>>((const float4*)x, (const float4*)Wq,
                             (const float4*)Wk, (const float4*)Wv,
                             (const float4*)Wo, (__half2*)xh, (__half2*)wh);

    // projections (fp16 MMA) -> fp16 q,k,v
    qkv_proj_h<<<dim3(8, 32, 3), 256>>>(xh, wh, q, k, v);

    // fp16 exp-scores (n-split, 3 CTAs/SM) + f32 row sums
    scores_exp_h<<<dim3(16, 16, BH), 256, SC_SMEM>>>(q, k, sch, lptr);

    // fp16 V^T per head
    transpose_v_h<<<dim3(SEQ / 32, DK / 32, BH), dim3(32, 8)>>>(v, vt);

    // attn emit + ctx GEMM (fp16 MMA, async pipelined) -> fp16 ctx
    fused_ctx_h<<<dim3(16, BH), 256, FC_SMEM>>>(sch, lptr, vt, attn, ch);

    if (y_out) {
        out_proj_h<<<dim3(8, 32), 256>>>(ch, wh, ob);
        bias_res_ln<<<ROWS, 256>>>(ob, x, bo, gamma, beta, y_out);
    }
}